// round 1
// baseline (speedup 1.0000x reference)
#include <cuda_runtime.h>
#include <cuda_bf16.h>

#define N_NODES  100000
#define N_EDGES  1600000
#define N_GRAPHS 64
#define HID      64
#define LN_EPS   1e-5f

// -------- persistent device scratch (no allocations allowed) --------
__device__ float  g_xl[N_NODES * HID];
__device__ float  g_xr[N_NODES * HID];
__device__ float  g_acc[N_NODES * HID];   // unnormalized sum_e ex * xl[src]
__device__ float  g_denom[N_NODES];       // sum_e ex
__device__ double g_S[N_GRAPHS];          // per-graph sum of s_n
__device__ int    g_cnt[N_GRAPHS];        // per-graph node count
__device__ double g_sum;                  // global sum of out
__device__ double g_sq;                   // global sum of out^2

// -------- kernel 0: zero the accumulators --------
__global__ void k_zero() {
    long i = (long)blockIdx.x * blockDim.x + threadIdx.x;
    long stride = (long)gridDim.x * blockDim.x;
    float4* acc4 = reinterpret_cast<float4*>(g_acc);
    const long n4 = (long)N_NODES * HID / 4;
    for (long t = i; t < n4; t += stride) acc4[t] = make_float4(0.f, 0.f, 0.f, 0.f);
    for (long t = i; t < N_NODES; t += stride) g_denom[t] = 0.f;
    if (i < N_GRAPHS) { g_S[i] = 0.0; g_cnt[i] = 0; }
    if (i == 0) { g_sum = 0.0; g_sq = 0.0; }
}

// -------- kernel 1: xl = x@W_l + b_l, xr = x@W_r + b_r --------
__global__ void k_transform(const float* __restrict__ x,
                            const float* __restrict__ Wl, const float* __restrict__ bl,
                            const float* __restrict__ Wr, const float* __restrict__ br) {
    int t = blockIdx.x * blockDim.x + threadIdx.x;
    if (t >= N_NODES * HID) return;
    int n = t >> 6;
    int c = t & 63;
    float x0 = x[n * 4 + 0], x1 = x[n * 4 + 1], x2 = x[n * 4 + 2], x3 = x[n * 4 + 3];
    float l = bl[c];
    l = fmaf(x0, Wl[c], l); l = fmaf(x1, Wl[64 + c], l);
    l = fmaf(x2, Wl[128 + c], l); l = fmaf(x3, Wl[192 + c], l);
    float r = br[c];
    r = fmaf(x0, Wr[c], r); r = fmaf(x1, Wr[64 + c], r);
    r = fmaf(x2, Wr[128 + c], r); r = fmaf(x3, Wr[192 + c], r);
    g_xl[t] = l;
    g_xr[t] = r;
}

// -------- kernel 2: per-edge attention + unnormalized aggregation --------
// warp = 2 edges; 16 lanes per edge; lane j handles channels [4j, 4j+4)
__global__ void k_edge(const int* __restrict__ ei, const float* __restrict__ att) {
    int gtid = blockIdx.x * blockDim.x + threadIdx.x;
    int lane = threadIdx.x & 31;
    int half = lane >> 4;           // which edge of the pair
    int j    = lane & 15;           // float4 index within row
    long e = (long)(gtid >> 5) * 2 + half;
    if (e >= N_EDGES) return;

    int src = ei[e];
    int dst = ei[N_EDGES + e];

    const float4* xl4 = reinterpret_cast<const float4*>(g_xl);
    const float4* xr4 = reinterpret_cast<const float4*>(g_xr);
    float4 a  = xl4[src * 16 + j];
    float4 b  = xr4[dst * 16 + j];
    float4 av = reinterpret_cast<const float4*>(att)[j];

    float h0 = a.x + b.x, h1 = a.y + b.y, h2 = a.z + b.z, h3 = a.w + b.w;
    // leaky_relu slope 0.2
    float l0 = fmaxf(h0, 0.f) + 0.2f * fminf(h0, 0.f);
    float l1 = fmaxf(h1, 0.f) + 0.2f * fminf(h1, 0.f);
    float l2 = fmaxf(h2, 0.f) + 0.2f * fminf(h2, 0.f);
    float l3 = fmaxf(h3, 0.f) + 0.2f * fminf(h3, 0.f);
    float p = l0 * av.x + l1 * av.y + l2 * av.z + l3 * av.w;

    // reduce across the 16 lanes of this edge (xor stays within the 16-group)
    p += __shfl_xor_sync(0xffffffffu, p, 8);
    p += __shfl_xor_sync(0xffffffffu, p, 4);
    p += __shfl_xor_sync(0xffffffffu, p, 2);
    p += __shfl_xor_sync(0xffffffffu, p, 1);

    float ex = __expf(p);   // softmax shift omitted: exact same alpha, |p| is O(1)

    if (j == 0) atomicAdd(&g_denom[dst], ex);

    float* outp = &g_acc[dst * HID + 4 * j];
    asm volatile("red.global.add.v4.f32 [%0], {%1,%2,%3,%4};"
                 :: "l"(outp), "f"(ex * a.x), "f"(ex * a.y), "f"(ex * a.z), "f"(ex * a.w)
                 : "memory");
}

// -------- kernel 3: node finalize + all reductions (LN stats, per-graph pool) --------
// warp per node; lane handles channels lane and lane+32
__global__ void k_node(const float* __restrict__ conv_bias,
                       const float* __restrict__ ln_w,
                       const float* __restrict__ lin_w,
                       const int*   __restrict__ batch) {
    __shared__ double sS[N_GRAPHS];
    __shared__ int    sC[N_GRAPHS];
    __shared__ double sSum, sSq;

    int tid = threadIdx.x;
    if (tid < N_GRAPHS) { sS[tid] = 0.0; sC[tid] = 0; }
    if (tid == 0) { sSum = 0.0; sSq = 0.0; }
    __syncthreads();

    int warp = (blockIdx.x * blockDim.x + tid) >> 5;
    int lane = tid & 31;
    int n = warp;   // grid sized exactly: N_NODES/8 blocks of 256

    float d = g_denom[n];
    float invd = d > 0.f ? 1.f / d : 0.f;
    float v0 = fmaxf(fmaf(g_acc[n * 64 + lane],      invd, conv_bias[lane]),      0.f);
    float v1 = fmaxf(fmaf(g_acc[n * 64 + 32 + lane], invd, conv_bias[lane + 32]), 0.f);

    float w0 = ln_w[lane]      * lin_w[lane];
    float w1 = ln_w[lane + 32] * lin_w[lane + 32];

    float s = v0 + v1;
    float q = v0 * v0 + v1 * v1;
    float t = v0 * w0 + v1 * w1;

    #pragma unroll
    for (int off = 16; off > 0; off >>= 1) {
        s += __shfl_xor_sync(0xffffffffu, s, off);
        q += __shfl_xor_sync(0xffffffffu, q, off);
        t += __shfl_xor_sync(0xffffffffu, t, off);
    }

    if (lane == 0) {
        int g = batch[n];
        atomicAdd(&sS[g], (double)t);
        atomicAdd(&sC[g], 1);
        atomicAdd(&sSum, (double)s);
        atomicAdd(&sSq,  (double)q);
    }
    __syncthreads();

    if (tid < N_GRAPHS) {
        if (sS[tid] != 0.0) atomicAdd(&g_S[tid], sS[tid]);
        if (sC[tid] != 0)   atomicAdd(&g_cnt[tid], sC[tid]);
    }
    if (tid == 0) {
        atomicAdd(&g_sum, sSum);
        atomicAdd(&g_sq,  sSq);
    }
}

// -------- kernel 4: final scalar combine + sigmoid --------
__global__ void k_final(const float* __restrict__ ln_w, const float* __restrict__ ln_b,
                        const float* __restrict__ lin_w, const float* __restrict__ lin_b,
                        float* __restrict__ out) {
    __shared__ float sW, sB;
    int t = threadIdx.x;
    if (t == 0) {
        float W = 0.f, B = 0.f;
        for (int i = 0; i < HID; i++) {
            W += ln_w[i] * lin_w[i];
            B += ln_b[i] * lin_w[i];
        }
        sW = W;
        sB = B + lin_b[0];
    }
    __syncthreads();

    double Ntot = (double)N_NODES * HID;
    double mu_d = g_sum / Ntot;
    double var_d = g_sq / Ntot - mu_d * mu_d;
    float mu  = (float)mu_d;
    float inv = rsqrtf((float)var_d + LN_EPS);

    float cnt = fmaxf((float)g_cnt[t], 1.f);
    float y = inv * ((float)g_S[t] / cnt - mu * sW) + sB;
    out[t] = 1.f / (1.f + __expf(-y));
}

extern "C" void kernel_launch(void* const* d_in, const int* in_sizes, int n_in,
                              void* d_out, int out_size) {
    const float* x         = (const float*)d_in[0];
    const int*   ei        = (const int*)  d_in[1];
    const int*   batch     = (const int*)  d_in[2];
    const float* W_l       = (const float*)d_in[3];
    const float* b_l       = (const float*)d_in[4];
    const float* W_r       = (const float*)d_in[5];
    const float* b_r       = (const float*)d_in[6];
    const float* att       = (const float*)d_in[7];
    const float* conv_bias = (const float*)d_in[8];
    const float* ln_w      = (const float*)d_in[9];
    const float* ln_b      = (const float*)d_in[10];
    const float* lin_w     = (const float*)d_in[11];
    const float* lin_b     = (const float*)d_in[12];
    float* out = (float*)d_out;

    k_zero<<<2048, 256>>>();
    k_transform<<<(N_NODES * HID + 255) / 256, 256>>>(x, W_l, b_l, W_r, b_r);
    k_edge<<<N_EDGES / 16, 256>>>(ei, att);         // 2 edges / warp, 8 warps / block
    k_node<<<N_NODES / 8, 256>>>(conv_bias, ln_w, lin_w, batch);
    k_final<<<1, N_GRAPHS>>>(ln_w, ln_b, lin_w, lin_b, out);
}